// round 1
// baseline (speedup 1.0000x reference)
#include <cuda_runtime.h>
#include <cstdint>

// Problem constants (fixed by reference)
#define B_  32
#define T_  1024
#define D_  256
#define NM  80
#define MM  8192    // MAX_MEL = T_TEXT * MAX_DUR

// Device scratch (no allocations allowed)
__device__ int   g_idx[B_ * MM];      // frame -> token index (only valid frames written)
__device__ int   g_len[B_];           // valid mel length per batch
__device__ float g_mu [B_ * NM * T_]; // per-token mel projection, layout [b][n][t]

// ---------------------------------------------------------------------------
// K1: inclusive scan of durations per batch + scatter frame->token map.
// Token t covers frames [cum[t]-dur[t], cum[t]) which exactly reproduces
// searchsorted(cum, p, side='right') incl. skipping zero-duration tokens.
// ---------------------------------------------------------------------------
__global__ void scan_build_idx(const int* __restrict__ dur) {
    __shared__ int s[T_];
    const int b = blockIdx.x;
    const int t = threadIdx.x;
    const int d = dur[b * T_ + t];
    s[t] = d;
    __syncthreads();
#pragma unroll
    for (int off = 1; off < T_; off <<= 1) {
        int v = (t >= off) ? s[t - off] : 0;
        __syncthreads();
        s[t] += v;
        __syncthreads();
    }
    const int end = s[t];
    for (int p = end - d; p < end; ++p) g_idx[b * MM + p] = t;
    if (t == T_ - 1) g_len[b] = end;
}

// ---------------------------------------------------------------------------
// K2: token-level GEMM  g_mu[b][n][t] = sum_d W[n][d]*E[b][t][d] + b_mu[n]
// Block: one (batch, 64-token tile), computes full 80 mel rows.
// Threads 256 as 16(t) x 16(n); thread tile 5n x 4t.
// E is staged TRANSPOSED in smem ([k][t], padded stride 68 for 16B-aligned
// conflict-free float4 reads over t).
// ---------------------------------------------------------------------------
#define TT 64   // token tile
#define KC 64   // k chunk
#define EPAD 68 // sE row stride in floats (16B aligned, low-conflict)

__global__ __launch_bounds__(256) void gemm_token_kernel(
    const float* __restrict__ E, const float* __restrict__ W,
    const float* __restrict__ bmu) {
    const int b  = blockIdx.y;
    const int t0 = blockIdx.x * TT;
    const int tid = threadIdx.x;
    const int tx = tid & 15;   // token dir (4 tokens each)
    const int ty = tid >> 4;   // mel dir   (5 mels each)

    __shared__ float sW[NM * KC];      // [n][k], row stride KC
    __shared__ float sE[KC * EPAD];    // [k][t], row stride EPAD

    float acc[5][4];
#pragma unroll
    for (int i = 0; i < 5; ++i)
#pragma unroll
        for (int j = 0; j < 4; ++j) acc[i][j] = 0.0f;

    for (int kc = 0; kc < D_; kc += KC) {
        // Load W chunk: 80x64 floats, float4-vectorized, coalesced.
        for (int q = tid; q < NM * (KC / 4); q += 256) {
            const int n  = q >> 4;          // KC/4 = 16 float4 per row
            const int kf = q & 15;
            float4 v = *reinterpret_cast<const float4*>(W + n * D_ + kc + kf * 4);
            *reinterpret_cast<float4*>(sW + n * KC + kf * 4) = v;
        }
        // Load E chunk transposed: read coalesced float4 over d, scatter to [k][t].
        for (int q = tid; q < TT * (KC / 4); q += 256) {
            const int t  = q >> 4;
            const int kf = q & 15;
            float4 v = *reinterpret_cast<const float4*>(
                E + ((size_t)b * T_ + t0 + t) * D_ + kc + kf * 4);
            const int k = kf * 4;
            sE[(k + 0) * EPAD + t] = v.x;
            sE[(k + 1) * EPAD + t] = v.y;
            sE[(k + 2) * EPAD + t] = v.z;
            sE[(k + 3) * EPAD + t] = v.w;
        }
        __syncthreads();

#pragma unroll 8
        for (int k = 0; k < KC; ++k) {
            float4 e = *reinterpret_cast<const float4*>(&sE[k * EPAD + tx * 4]);
            float w0 = sW[(ty * 5 + 0) * KC + k];
            float w1 = sW[(ty * 5 + 1) * KC + k];
            float w2 = sW[(ty * 5 + 2) * KC + k];
            float w3 = sW[(ty * 5 + 3) * KC + k];
            float w4 = sW[(ty * 5 + 4) * KC + k];
            acc[0][0] += w0 * e.x; acc[0][1] += w0 * e.y; acc[0][2] += w0 * e.z; acc[0][3] += w0 * e.w;
            acc[1][0] += w1 * e.x; acc[1][1] += w1 * e.y; acc[1][2] += w1 * e.z; acc[1][3] += w1 * e.w;
            acc[2][0] += w2 * e.x; acc[2][1] += w2 * e.y; acc[2][2] += w2 * e.z; acc[2][3] += w2 * e.w;
            acc[3][0] += w3 * e.x; acc[3][1] += w3 * e.y; acc[3][2] += w3 * e.z; acc[3][3] += w3 * e.w;
            acc[4][0] += w4 * e.x; acc[4][1] += w4 * e.y; acc[4][2] += w4 * e.z; acc[4][3] += w4 * e.w;
        }
        __syncthreads();
    }

    // Epilogue: add bias, store float4 to g_mu[b][n][t]
#pragma unroll
    for (int i = 0; i < 5; ++i) {
        const int n = ty * 5 + i;
        const float bv = bmu[n];
        float4 r;
        r.x = acc[i][0] + bv;
        r.y = acc[i][1] + bv;
        r.z = acc[i][2] + bv;
        r.w = acc[i][3] + bv;
        *reinterpret_cast<float4*>(g_mu + ((size_t)b * NM + n) * T_ + t0 + tx * 4) = r;
    }
}

// ---------------------------------------------------------------------------
// K3: scatter per-token mu columns into out[b][n][p]; zero padding frames;
// optionally append mel_mask as float (0/1) after the mu block.
// ---------------------------------------------------------------------------
__global__ __launch_bounds__(256) void upsample_store(float* __restrict__ out,
                                                      int write_mask) {
    const int b = blockIdx.y;
    const int p = blockIdx.x * blockDim.x + threadIdx.x;
    const int L = g_len[b];
    const bool valid = p < L;

    float* obase = out + (size_t)b * NM * MM + p;
    if (valid) {
        const int t = g_idx[b * MM + p];
        const float* mrow = g_mu + (size_t)b * NM * T_ + t;
#pragma unroll 16
        for (int n = 0; n < NM; ++n) {
            obase[(size_t)n * MM] = mrow[(size_t)n * T_];
        }
    } else {
#pragma unroll 16
        for (int n = 0; n < NM; ++n) {
            obase[(size_t)n * MM] = 0.0f;
        }
    }
    if (write_mask) {
        out[(size_t)B_ * NM * MM + (size_t)b * MM + p] = valid ? 1.0f : 0.0f;
    }
}

// ---------------------------------------------------------------------------
extern "C" void kernel_launch(void* const* d_in, const int* in_sizes, int n_in,
                              void* d_out, int out_size) {
    const float* E   = nullptr;
    const int*   dur = nullptr;
    const float* W   = nullptr;
    const float* bmu = nullptr;
    for (int i = 0; i < n_in; ++i) {
        switch (in_sizes[i]) {
            case B_ * T_ * D_: E   = (const float*)d_in[i]; break;
            case B_ * T_:      dur = (const int*)  d_in[i]; break;
            case NM * D_:      W   = (const float*)d_in[i]; break;
            case NM:           bmu = (const float*)d_in[i]; break;
            default: break;
        }
    }
    float* out = (float*)d_out;
    const int mu_elems = B_ * NM * MM;          // 20,971,520
    const int write_mask = (out_size >= mu_elems + B_ * MM) ? 1 : 0;

    scan_build_idx<<<B_, T_>>>(dur);
    gemm_token_kernel<<<dim3(T_ / TT, B_), 256>>>(E, W, bmu);
    upsample_store<<<dim3(MM / 256, B_), 256>>>(out, write_mask);
}